// round 16
// baseline (speedup 1.0000x reference)
#include <cuda_runtime.h>
#include <cuda_bf16.h>
#include <math.h>
#include <stdint.h>

#define BNS 0.9995003746f  // float32(1/sqrt(1+1e-3))

#define B  8
#define NP 2048
#define KNN 64
#define TU 256
#define FEAT 576   // 3*K*3
#define M_TOT (B*NP)   // 16384

// ---------------- scratch (device globals; no allocation allowed) ----------------
__device__ float g_xmax[B*TU];
__device__ float g_T[B*9];
__device__ float g_pts[B*NP*3];

// activations as bf16 hi/lo pairs
__device__ __align__(16) __nv_bfloat16 g_ah[M_TOT*FEAT];
__device__ __align__(16) __nv_bfloat16 g_al[M_TOT*FEAT];
__device__ __align__(16) __nv_bfloat16 g_f0h[M_TOT*512];
__device__ __align__(16) __nv_bfloat16 g_f0l[M_TOT*512];
__device__ __align__(16) __nv_bfloat16 g_f1h[M_TOT*512];
__device__ __align__(16) __nv_bfloat16 g_f1l[M_TOT*512];

// transposed+split weights [Npad, K]  (row-major, K contiguous)
__device__ __align__(16) __nv_bfloat16 g_w1h[512*576],  g_w1l[512*576];
__device__ __align__(16) __nv_bfloat16 g_wrh[512*512],  g_wrl[512*512];
__device__ __align__(16) __nv_bfloat16 g_wb1h[512*512], g_wb1l[512*512];
__device__ __align__(16) __nv_bfloat16 g_wb2h[256*512], g_wb2l[256*512];
__device__ __align__(16) __nv_bfloat16 g_wb3h[256*256], g_wb3l[256*256];

// ---------------- PTX helpers ----------------
__device__ __forceinline__ uint32_t s2u(const void* p) {
    uint32_t a;
    asm("{ .reg .u64 t; cvta.to.shared.u64 t, %1; cvt.u32.u64 %0, t; }" : "=r"(a) : "l"(p));
    return a;
}
__device__ __forceinline__ void cpa16(uint32_t saddr, const void* g) {
    asm volatile("cp.async.cg.shared.global [%0], [%1], 16;" :: "r"(saddr), "l"(g));
}
__device__ __forceinline__ void ldm4(uint32_t* r, uint32_t a) {
    asm volatile("ldmatrix.sync.aligned.m8n8.x4.shared.b16 {%0,%1,%2,%3}, [%4];"
                 : "=r"(r[0]), "=r"(r[1]), "=r"(r[2]), "=r"(r[3]) : "r"(a));
}
__device__ __forceinline__ void mma16816(float* d, const uint32_t* a, const uint32_t* b) {
    asm volatile("mma.sync.aligned.m16n8k16.row.col.f32.bf16.bf16.f32 "
                 "{%0,%1,%2,%3}, {%4,%5,%6,%7}, {%8,%9}, {%0,%1,%2,%3};"
                 : "+f"(d[0]), "+f"(d[1]), "+f"(d[2]), "+f"(d[3])
                 : "r"(a[0]), "r"(a[1]), "r"(a[2]), "r"(a[3]), "r"(b[0]), "r"(b[1]));
}
__device__ __forceinline__ uint32_t swz(uint32_t off) { return off ^ ((off >> 3) & 0x70); }

// ---------------- T-Net stage 1 ----------------
__global__ void tnet_conv_max(const float* __restrict__ points,
                              const float* __restrict__ tw, const float* __restrict__ tb,
                              const float* __restrict__ tg1, const float* __restrict__ tbt1,
                              float* __restrict__ xmax)
{
    __shared__ float P[NP*3];
    int b = blockIdx.x, u = threadIdx.x;
    const float* pb = points + b*NP*3;
    for (int t = u; t < NP*3; t += TU) P[t] = pb[t];
    __syncthreads();
    float w0 = tw[u], w1 = tw[TU+u], w2 = tw[2*TU+u], bb = tb[u];
    float al = tg1[u]*BNS, bt = tbt1[u];
    float m = 0.f;
    for (int n = 0; n < NP; n++) {
        float z = P[n*3]*w0 + P[n*3+1]*w1 + P[n*3+2]*w2 + bb;
        z = fmaxf(z*al + bt, 0.f);
        m = fmaxf(m, z);
    }
    xmax[b*TU+u] = m;
}

// ---------------- T-Net stage 2 ----------------
__global__ void tnet_dense(const float* __restrict__ xmax,
                           const float* __restrict__ td1w, const float* __restrict__ td1b,
                           const float* __restrict__ tg2, const float* __restrict__ tbt2,
                           const float* __restrict__ td2w, const float* __restrict__ td2b,
                           float* __restrict__ Tout)
{
    __shared__ float xm[TU];
    __shared__ float x2[TU];
    int b = blockIdx.x, u = threadIdx.x;
    xm[u] = xmax[b*TU+u];
    __syncthreads();
    float s = td1b[u];
    for (int v = 0; v < TU; v++) s += xm[v]*td1w[v*TU+u];
    s = fmaxf(s*(tg2[u]*BNS) + tbt2[u], 0.f);
    x2[u] = s;
    __syncthreads();
    if (u < 9) {
        float t = td2b[u];
        for (int v = 0; v < TU; v++) t += x2[v]*td2w[v*9+u];
        Tout[b*9+u] = t;
    }
}

// ---------------- apply T ----------------
__global__ void transform_pts(const float* __restrict__ points,
                              const float* __restrict__ Tm, float* __restrict__ pts)
{
    int i = blockIdx.x*256 + threadIdx.x;
    if (i >= M_TOT) return;
    int b = i >> 11;
    const float* T = Tm + b*9;
    float x = points[i*3], y = points[i*3+1], z = points[i*3+2];
    pts[i*3+0] = x*T[0] + y*T[3] + z*T[6];
    pts[i*3+1] = x*T[1] + y*T[4] + z*T[7];
    pts[i*3+2] = x*T[2] + y*T[5] + z*T[8];
}

// ---------------- weight prep: transpose [K,N] -> [Npad,K], split hi/lo bf16 ----------------
__global__ void prep_w(const float* __restrict__ W, __nv_bfloat16* __restrict__ wh,
                       __nv_bfloat16* __restrict__ wl, int K, int N, int Npad)
{
    int i = blockIdx.x*256 + threadIdx.x;
    if (i >= Npad*K) return;
    int n = i / K, k = i - n*K;
    float v = (n < N) ? W[(size_t)k*N + n] : 0.f;
    __nv_bfloat16 h = __float2bfloat16(v);
    wh[i] = h;
    wl[i] = __float2bfloat16(v - __bfloat162float(h));
}

// ---------------- ball query + stable top-K + gather -> feats (bf16 hi/lo) ----------------
__global__ void ballquery_kernel(const float* __restrict__ noise,
                                 __nv_bfloat16* __restrict__ fh, __nv_bfloat16* __restrict__ fl)
{
    extern __shared__ char smraw[];
    float* ptsS = (float*)smraw;                        // 6144 floats
    float* noiS = ptsS + NP*3;                          // 2048
    float* dS   = noiS + NP;                            // 2048
    unsigned long long* buf = (unsigned long long*)(dS + NP); // 2048 u64
    int* idxS = (int*)(buf + NP);                       // 64
    __shared__ int cnt;

    int b = blockIdx.x >> 11;
    int i = blockIdx.x & (NP-1);
    int tid = threadIdx.x;

    const float* pg = g_pts + b*NP*3;
    for (int t = tid; t < NP*3; t += 256) ptsS[t] = pg[t];
    const float* ng = noise + ((size_t)b*NP + i)*NP;
    for (int t = tid; t < NP; t += 256) noiS[t] = ng[t];
    __syncthreads();

    float px = ptsS[i*3], py = ptsS[i*3+1], pz = ptsS[i*3+2];
    for (int j = tid; j < NP; j += 256) {
        float dx = px - ptsS[j*3], dy = py - ptsS[j*3+1], dz = pz - ptsS[j*3+2];
        dS[j] = sqrtf(dx*dx + dy*dy + dz*dz);
    }
    __syncthreads();

    const float radii[3] = {0.1f, 0.3f, 0.7f};
    __nv_bfloat16* foh = fh + ((size_t)blockIdx.x)*FEAT;
    __nv_bfloat16* fol = fl + ((size_t)blockIdx.x)*FEAT;

    for (int r = 0; r < 3; r++) {
        float rad = radii[r];
        if (tid == 0) cnt = 0;
        __syncthreads();
        for (int j = tid; j < NP; j += 256) {
            float sc = noiS[j];
            if (dS[j] <= rad && sc > 0.f) {
                int p = atomicAdd(&cnt, 1);
                buf[p] = ((unsigned long long)__float_as_uint(sc) << 32)
                       | (unsigned)(0xFFFFFFFFu - (unsigned)j);
            }
        }
        __syncthreads();
        int c = cnt;
        int S = 64; while (S < c) S <<= 1;
        for (int t = c + tid; t < S; t += 256) buf[t] = 0ULL;
        __syncthreads();
        for (int k = 2; k <= S; k <<= 1) {
            for (int jj = k >> 1; jj > 0; jj >>= 1) {
                for (int t = tid; t < S; t += 256) {
                    int ixj = t ^ jj;
                    if (ixj > t) {
                        bool desc = ((t & k) == 0);
                        unsigned long long x = buf[t], y = buf[ixj];
                        if ((x < y) == desc) { buf[t] = y; buf[ixj] = x; }
                    }
                }
                __syncthreads();
            }
        }
        int cc = c < KNN ? c : KNN;
        if (tid < KNN && tid < cc)
            idxS[tid] = (int)(0xFFFFFFFFu - (unsigned)(buf[tid] & 0xFFFFFFFFu));
        __syncthreads();
        if (tid == 0 && c < KNN) {
            int w = c;
            for (int j = 0; j < NP && w < KNN; j++)
                if (!(dS[j] <= rad && noiS[j] > 0.f)) idxS[w++] = j;
        }
        __syncthreads();
        for (int t = tid; t < KNN*3; t += 256) {
            int k = t / 3, co = t % 3;
            float v = ptsS[idxS[k]*3 + co];
            int o = k*9 + r*3 + co;
            __nv_bfloat16 h = __float2bfloat16(v);
            foh[o] = h;
            fol[o] = __float2bfloat16(v - __bfloat162float(h));
        }
        __syncthreads();
    }
}

// ---------------- bf16-split mma.sync GEMM: D = A @ W^T, epilogue fused ----------------
// A: [M,K] hi/lo bf16 (ldA), W: [Npad,K] hi/lo bf16 (K contiguous)
// CTA 128x128, 8 warps at 32(M) x 64(N), Ktile=64 double-buffered via cp.async.
// MODE 0: relu(bn(acc+bias)) -> hi/lo bf16 out (ldO)
// MODE 1: acc + bias + (Rh+Rl) -> hi/lo bf16 out
// MODE 2: relu(bn(acc+bias)), n<Nvalid -> atomicMax out[batch*Nvalid+n]
template<int MODE>
__global__ __launch_bounds__(256, 1)
void gemm_mma(const __nv_bfloat16* __restrict__ Ah, const __nv_bfloat16* __restrict__ Al,
              const __nv_bfloat16* __restrict__ Wh, const __nv_bfloat16* __restrict__ Wl,
              const float* __restrict__ bias, const float* __restrict__ gamma,
              const float* __restrict__ beta,
              const __nv_bfloat16* __restrict__ Rh, const __nv_bfloat16* __restrict__ Rl,
              __nv_bfloat16* __restrict__ Oh, __nv_bfloat16* __restrict__ Ol,
              float* __restrict__ outF,
              int K, int ldA, int ldO, int Nvalid)
{
    extern __shared__ char dsm[];
    uint32_t sb0 = s2u(dsm);
    uint32_t sbase = (sb0 + 1023u) & ~1023u;

    const int tid = threadIdx.x, wid = tid >> 5, lane = tid & 31;
    const int row0 = blockIdx.y * 128, col0 = blockIdx.x * 128;
    const int wm = wid >> 1;   // 0..3 -> rows wm*32
    const int wn = wid & 1;    // 0..1 -> cols wn*64

    float acc[2][8][4];
    #pragma unroll
    for (int m = 0; m < 2; m++)
        #pragma unroll
        for (int n = 0; n < 8; n++)
            #pragma unroll
            for (int q = 0; q < 4; q++) acc[m][n][q] = 0.f;

    // stage layout (64 KB): Ah@0, Al@16K, Wh@32K, Wl@48K; two stages.
    const int S = K >> 6;

    // per-thread load coords: 4 chunks per tile
    int lrow[4], lcq[4]; uint32_t lsw[4];
    #pragma unroll
    for (int it = 0; it < 4; it++) {
        int c = tid + 256*it;
        lrow[it] = c >> 3; lcq[it] = c & 7;
        lsw[it] = swz((uint32_t)(lrow[it]*128 + lcq[it]*16));
    }

    auto load_stage = [&](int s, int bf) {
        uint32_t sb = sbase + bf*65536;
        int k0 = s << 6;
        #pragma unroll
        for (int it = 0; it < 4; it++) {
            int row = lrow[it], cq = lcq[it];
            size_t aoff = (size_t)(row0 + row)*ldA + k0 + cq*8;
            size_t woff = (size_t)(col0 + row)*K   + k0 + cq*8;
            cpa16(sb + lsw[it],          Ah + aoff);
            cpa16(sb + 16384 + lsw[it],  Al + aoff);
            cpa16(sb + 32768 + lsw[it],  Wh + woff);
            cpa16(sb + 49152 + lsw[it],  Wl + woff);
        }
        asm volatile("cp.async.commit_group;" ::: "memory");
    };

    load_stage(0, 0);

    for (int s = 0; s < S; s++) {
        if (s + 1 < S) load_stage(s + 1, (s + 1) & 1);
        if (s + 1 < S) asm volatile("cp.async.wait_group 1;" ::: "memory");
        else           asm volatile("cp.async.wait_group 0;" ::: "memory");
        __syncthreads();

        uint32_t sb = sbase + (s & 1)*65536;
        #pragma unroll
        for (int kk = 0; kk < 4; kk++) {
            // A fragments (hi & lo) for 2 m-tiles
            uint32_t afh[2][4], afl[2][4];
            #pragma unroll
            for (int m = 0; m < 2; m++) {
                uint32_t off = (uint32_t)((wm*32 + m*16 + (lane & 15))*128
                                          + kk*32 + ((lane >> 4) << 4));
                uint32_t sw = swz(off);
                ldm4(afh[m], sb + sw);
                ldm4(afl[m], sb + 16384 + sw);
            }
            // B fragments (hi & lo) for 4 n-tile pairs
            uint32_t bfh[4][4], bfl[4][4];
            #pragma unroll
            for (int np = 0; np < 4; np++) {
                int q = lane >> 3, rr = lane & 7;
                uint32_t off = (uint32_t)((wn*64 + np*16 + rr + ((q >> 1) << 3))*128
                                          + kk*32 + ((q & 1) << 4));
                uint32_t sw = swz(off);
                ldm4(bfh[np], sb + 32768 + sw);
                ldm4(bfl[np], sb + 49152 + sw);
            }
            #pragma unroll
            for (int m = 0; m < 2; m++)
                #pragma unroll
                for (int nt = 0; nt < 8; nt++) {
                    int np = nt >> 1, hf = (nt & 1)*2;
                    uint32_t bh[2] = { bfh[np][hf], bfh[np][hf+1] };
                    uint32_t bl[2] = { bfl[np][hf], bfl[np][hf+1] };
                    mma16816(acc[m][nt], afh[m], bh);
                    mma16816(acc[m][nt], afh[m], bl);
                    mma16816(acc[m][nt], afl[m], bh);
                }
        }
        __syncthreads();
    }

    // ---- epilogue ----
    #pragma unroll
    for (int m = 0; m < 2; m++) {
        #pragma unroll
        for (int nt = 0; nt < 8; nt++) {
            int baseRow = row0 + wm*32 + m*16 + (lane >> 2);
            int baseCol = col0 + wn*64 + nt*8 + (lane & 3)*2;
            #pragma unroll
            for (int q = 0; q < 4; q++) {
                int rr = baseRow + (q >> 1)*8;
                int n  = baseCol + (q & 1);
                float v = acc[m][nt][q];
                if (MODE == 0) {
                    float al = gamma[n]*BNS;
                    v = fmaxf(v*al + (bias[n]*al + beta[n]), 0.f);
                    __nv_bfloat16 h = __float2bfloat16(v);
                    Oh[(size_t)rr*ldO + n] = h;
                    Ol[(size_t)rr*ldO + n] = __float2bfloat16(v - __bfloat162float(h));
                } else if (MODE == 1) {
                    float res = __bfloat162float(Rh[(size_t)rr*ldO + n])
                              + __bfloat162float(Rl[(size_t)rr*ldO + n]);
                    v = v + bias[n] + res;
                    __nv_bfloat16 h = __float2bfloat16(v);
                    Oh[(size_t)rr*ldO + n] = h;
                    Ol[(size_t)rr*ldO + n] = __float2bfloat16(v - __bfloat162float(h));
                } else {
                    if (n < Nvalid) {
                        float al = gamma[n]*BNS;
                        v = fmaxf(v*al + (bias[n]*al + beta[n]), 0.f);
                        atomicMax((unsigned int*)&outF[(size_t)(rr >> 11)*Nvalid + n],
                                  __float_as_uint(v));
                    }
                }
            }
        }
    }
}

__global__ void init_out(float* out) {
    int i = blockIdx.x*256 + threadIdx.x;
    if (i < B*170) out[i] = 0.f;
}

// ---------------- launch ----------------
extern "C" void kernel_launch(void* const* d_in, const int* in_sizes, int n_in,
                              void* d_out, int out_size)
{
    const float* points = (const float*)d_in[0];
    const float* noise  = (const float*)d_in[1];
    const float* tw   = (const float*)d_in[2];
    const float* tb   = (const float*)d_in[3];
    const float* tg1  = (const float*)d_in[4];
    const float* tbt1 = (const float*)d_in[5];
    const float* td1w = (const float*)d_in[6];
    const float* td1b = (const float*)d_in[7];
    const float* tg2  = (const float*)d_in[8];
    const float* tbt2 = (const float*)d_in[9];
    const float* td2w = (const float*)d_in[10];
    const float* td2b = (const float*)d_in[11];
    const float* c1w  = (const float*)d_in[12];
    const float* c1b  = (const float*)d_in[13];
    const float* g1   = (const float*)d_in[14];
    const float* be1  = (const float*)d_in[15];
    const float* rw   = (const float*)d_in[16];
    const float* rb   = (const float*)d_in[17];
    const float* b1w  = (const float*)d_in[18];
    const float* b1b  = (const float*)d_in[19];
    const float* b1g  = (const float*)d_in[20];
    const float* b1be = (const float*)d_in[21];
    const float* b2w  = (const float*)d_in[22];
    const float* b2b  = (const float*)d_in[23];
    const float* b2g  = (const float*)d_in[24];
    const float* b2be = (const float*)d_in[25];
    const float* b3w  = (const float*)d_in[26];
    const float* b3b  = (const float*)d_in[27];
    const float* b3g  = (const float*)d_in[28];
    const float* b3be = (const float*)d_in[29];
    float* out = (float*)d_out;

    float *xmax, *Tm, *pts;
    __nv_bfloat16 *ah, *al, *f0h, *f0l, *f1h, *f1l;
    __nv_bfloat16 *w1h, *w1l, *wrh, *wrl, *wb1h, *wb1l, *wb2h, *wb2l, *wb3h, *wb3l;
    cudaGetSymbolAddress((void**)&xmax, g_xmax);
    cudaGetSymbolAddress((void**)&Tm,   g_T);
    cudaGetSymbolAddress((void**)&pts,  g_pts);
    cudaGetSymbolAddress((void**)&ah,  g_ah);   cudaGetSymbolAddress((void**)&al,  g_al);
    cudaGetSymbolAddress((void**)&f0h, g_f0h);  cudaGetSymbolAddress((void**)&f0l, g_f0l);
    cudaGetSymbolAddress((void**)&f1h, g_f1h);  cudaGetSymbolAddress((void**)&f1l, g_f1l);
    cudaGetSymbolAddress((void**)&w1h, g_w1h);  cudaGetSymbolAddress((void**)&w1l, g_w1l);
    cudaGetSymbolAddress((void**)&wrh, g_wrh);  cudaGetSymbolAddress((void**)&wrl, g_wrl);
    cudaGetSymbolAddress((void**)&wb1h, g_wb1h); cudaGetSymbolAddress((void**)&wb1l, g_wb1l);
    cudaGetSymbolAddress((void**)&wb2h, g_wb2h); cudaGetSymbolAddress((void**)&wb2l, g_wb2l);
    cudaGetSymbolAddress((void**)&wb3h, g_wb3h); cudaGetSymbolAddress((void**)&wb3l, g_wb3l);

    init_out<<<(B*170 + 255)/256, 256>>>(out);

    // weight prep (transpose + bf16 split)
    prep_w<<<(512*576 + 255)/256, 256>>>(c1w, w1h, w1l, 576, 512, 512);
    prep_w<<<(512*512 + 255)/256, 256>>>(rw,  wrh, wrl, 512, 512, 512);
    prep_w<<<(512*512 + 255)/256, 256>>>(b1w, wb1h, wb1l, 512, 512, 512);
    prep_w<<<(256*512 + 255)/256, 256>>>(b2w, wb2h, wb2l, 512, 256, 256);
    prep_w<<<(256*256 + 255)/256, 256>>>(b3w, wb3h, wb3l, 256, 170, 256);

    // T-Net
    tnet_conv_max<<<B, TU>>>(points, tw, tb, tg1, tbt1, xmax);
    tnet_dense<<<B, TU>>>(xmax, td1w, td1b, tg2, tbt2, td2w, td2b, Tm);
    transform_pts<<<(M_TOT + 255)/256, 256>>>(points, Tm, pts);

    // ball query + gather (writes feats as bf16 hi/lo)
    const int SMEM_SEL = (NP*3 + NP + NP)*4 + NP*8 + KNN*4;  // 57600 B
    cudaFuncSetAttribute(ballquery_kernel, cudaFuncAttributeMaxDynamicSharedMemorySize, SMEM_SEL);
    ballquery_kernel<<<M_TOT, 256, SMEM_SEL>>>(noise, ah, al);

    // tensor-core MLP stack (mma.sync bf16 hi/lo split)
    const int SMEM_TC = 2*65536 + 1024;
    cudaFuncSetAttribute(gemm_mma<0>, cudaFuncAttributeMaxDynamicSharedMemorySize, SMEM_TC);
    cudaFuncSetAttribute(gemm_mma<1>, cudaFuncAttributeMaxDynamicSharedMemorySize, SMEM_TC);
    cudaFuncSetAttribute(gemm_mma<2>, cudaFuncAttributeMaxDynamicSharedMemorySize, SMEM_TC);

    // G1: feats[M,576] @ c1w -> f0 (BN+ReLU)
    gemm_mma<0><<<dim3(4,128), 256, SMEM_TC>>>(ah, al, w1h, w1l, c1b, g1, be1,
                                               nullptr, nullptr, f0h, f0l, nullptr,
                                               576, 576, 512, 512);
    // G2: f1 = f0 + f0@rw + rb
    gemm_mma<1><<<dim3(4,128), 256, SMEM_TC>>>(f0h, f0l, wrh, wrl, rb, nullptr, nullptr,
                                               f0h, f0l, f1h, f1l, nullptr,
                                               512, 512, 512, 512);
    // G3: block1 (BN+ReLU) -> f0
    gemm_mma<0><<<dim3(4,128), 256, SMEM_TC>>>(f1h, f1l, wb1h, wb1l, b1b, b1g, b1be,
                                               nullptr, nullptr, f0h, f0l, nullptr,
                                               512, 512, 512, 512);
    // G4: block2 (BN+ReLU), N=256 -> f1 (ld 256)
    gemm_mma<0><<<dim3(2,128), 256, SMEM_TC>>>(f0h, f0l, wb2h, wb2l, b2b, b2g, b2be,
                                               nullptr, nullptr, f1h, f1l, nullptr,
                                               512, 512, 256, 256);
    // G5: block3 (BN+ReLU) + max-pool over points -> out[8,170]
    gemm_mma<2><<<dim3(2,128), 256, SMEM_TC>>>(f1h, f1l, wb3h, wb3l, b3b, b3g, b3be,
                                               nullptr, nullptr, nullptr, nullptr, out,
                                               256, 256, 0, 170);
}

// round 17
// speedup vs baseline: 1.0911x; 1.0911x over previous
#include <cuda_runtime.h>
#include <math.h>
#include <stdint.h>

#define BNS 0.9995003746f  // float32(1/sqrt(1+1e-3))

#define B  8
#define NP 2048
#define KNN 64
#define TU 256
#define FEAT 576   // 3*K*3
#define M_TOT (B*NP)   // 16384

// ---------------- scratch (device globals; no allocation allowed) ----------------
__device__ float g_xmax[B*TU];
__device__ float g_T[B*9];
__device__ float g_feats[M_TOT*FEAT];     // 37.7 MB
__device__ float g_f0[M_TOT*512];         // 33.5 MB
__device__ float g_f1[M_TOT*512];         // 33.5 MB

// ---------------- T-Net stage 1: 1x1 conv + BN + ReLU + global max over N ----------------
__global__ void tnet_conv_max(const float* __restrict__ points,
                              const float* __restrict__ tw, const float* __restrict__ tb,
                              const float* __restrict__ tg1, const float* __restrict__ tbt1,
                              float* __restrict__ xmax)
{
    __shared__ float P[NP*3];
    int b = blockIdx.x, u = threadIdx.x;
    const float* pb = points + b*NP*3;
    for (int t = u; t < NP*3; t += TU) P[t] = pb[t];
    __syncthreads();
    float w0 = tw[u], w1 = tw[TU+u], w2 = tw[2*TU+u], bb = tb[u];
    float al = tg1[u]*BNS, bt = tbt1[u];
    float m = 0.f;
    for (int n = 0; n < NP; n++) {
        float z = P[n*3]*w0 + P[n*3+1]*w1 + P[n*3+2]*w2 + bb;
        z = fmaxf(z*al + bt, 0.f);
        m = fmaxf(m, z);
    }
    xmax[b*TU+u] = m;
}

// ---------------- T-Net stage 2: dense->BN->ReLU, then 9-wide dense -> T matrix ----------------
__global__ void tnet_dense(const float* __restrict__ xmax,
                           const float* __restrict__ td1w, const float* __restrict__ td1b,
                           const float* __restrict__ tg2, const float* __restrict__ tbt2,
                           const float* __restrict__ td2w, const float* __restrict__ td2b,
                           float* __restrict__ Tout)
{
    __shared__ float xm[TU];
    __shared__ float x2[TU];
    int b = blockIdx.x, u = threadIdx.x;
    xm[u] = xmax[b*TU+u];
    __syncthreads();
    float s = td1b[u];
    for (int v = 0; v < TU; v++) s += xm[v]*td1w[v*TU+u];
    s = fmaxf(s*(tg2[u]*BNS) + tbt2[u], 0.f);
    x2[u] = s;
    __syncthreads();
    if (u < 9) {
        float t = td2b[u];
        for (int v = 0; v < TU; v++) t += x2[v]*td2w[v*9+u];
        Tout[b*9+u] = t;
    }
}

// ---------------- ball query (with fused point transform) + stable top-K + gather ----------------
// one block (256 threads) per (b,i); exact argsort(-score) semantics.
__global__ void ballquery_kernel(const float* __restrict__ points,
                                 const float* __restrict__ noise,
                                 float* __restrict__ feats)
{
    extern __shared__ char smraw[];
    float* ptsS = (float*)smraw;                        // 6144 floats
    float* noiS = ptsS + NP*3;                          // 2048
    float* dS   = noiS + NP;                            // 2048
    unsigned long long* buf = (unsigned long long*)(dS + NP); // 2048 u64
    int* idxS = (int*)(buf + NP);                       // 64
    __shared__ int cnt;

    int b = blockIdx.x >> 11;
    int i = blockIdx.x & (NP-1);
    int tid = threadIdx.x;

    // load raw points + noise
    const float* pb = points + b*NP*3;
    for (int t = tid; t < NP*3; t += 256) ptsS[t] = pb[t];
    const float* ng = noise + ((size_t)b*NP + i)*NP;
    for (int t = tid; t < NP; t += 256) noiS[t] = ng[t];
    __syncthreads();

    // fused transform: pts = points @ T  (in-place, each thread owns whole points)
    {
        const float* T = g_T + b*9;
        float T0=T[0],T1=T[1],T2=T[2],T3=T[3],T4=T[4],T5=T[5],T6=T[6],T7=T[7],T8=T[8];
        for (int j = tid; j < NP; j += 256) {
            float x = ptsS[j*3], y = ptsS[j*3+1], z = ptsS[j*3+2];
            ptsS[j*3+0] = x*T0 + y*T3 + z*T6;
            ptsS[j*3+1] = x*T1 + y*T4 + z*T7;
            ptsS[j*3+2] = x*T2 + y*T5 + z*T8;
        }
    }
    __syncthreads();

    float px = ptsS[i*3], py = ptsS[i*3+1], pz = ptsS[i*3+2];
    for (int j = tid; j < NP; j += 256) {
        float dx = px - ptsS[j*3], dy = py - ptsS[j*3+1], dz = pz - ptsS[j*3+2];
        dS[j] = sqrtf(dx*dx + dy*dy + dz*dz);
    }
    __syncthreads();

    const float radii[3] = {0.1f, 0.3f, 0.7f};
    float* fout = feats + ((size_t)blockIdx.x)*FEAT;

    for (int r = 0; r < 3; r++) {
        float rad = radii[r];
        if (tid == 0) cnt = 0;
        __syncthreads();
        for (int j = tid; j < NP; j += 256) {
            float sc = noiS[j];
            if (dS[j] <= rad && sc > 0.f) {
                int p = atomicAdd(&cnt, 1);
                buf[p] = ((unsigned long long)__float_as_uint(sc) << 32)
                       | (unsigned)(0xFFFFFFFFu - (unsigned)j);
            }
        }
        __syncthreads();
        int c = cnt;
        int S = 64; while (S < c) S <<= 1;
        for (int t = c + tid; t < S; t += 256) buf[t] = 0ULL;
        __syncthreads();
        // bitonic sort, descending (keys unique -> deterministic result)
        for (int k = 2; k <= S; k <<= 1) {
            for (int jj = k >> 1; jj > 0; jj >>= 1) {
                for (int t = tid; t < S; t += 256) {
                    int ixj = t ^ jj;
                    if (ixj > t) {
                        bool desc = ((t & k) == 0);
                        unsigned long long x = buf[t], y = buf[ixj];
                        if ((x < y) == desc) { buf[t] = y; buf[ixj] = x; }
                    }
                }
                __syncthreads();
            }
        }
        int cc = c < KNN ? c : KNN;
        if (tid < KNN && tid < cc)
            idxS[tid] = (int)(0xFFFFFFFFu - (unsigned)(buf[tid] & 0xFFFFFFFFu));
        __syncthreads();
        if (tid == 0 && c < KNN) {
            int w = c;
            for (int j = 0; j < NP && w < KNN; j++)
                if (!(dS[j] <= rad && noiS[j] > 0.f)) idxS[w++] = j;
        }
        __syncthreads();
        for (int t = tid; t < KNN*3; t += 256) {
            int k = t / 3, co = t % 3;
            fout[k*9 + r*3 + co] = ptsS[idxS[k]*3 + co];
        }
        __syncthreads();
    }
}

// ---------------- double-buffered fused SGEMM: C = epilogue(A[M,K] @ W[K,N]) ----------------
// MODE 0: relu(bn(acc + bias, gamma, beta))          -> out[m*N+n]
// MODE 1: resIn[m*N+n] + acc + bias[n]               -> out[m*N+n]
// MODE 2: relu(bn(...)) then atomicMax into out[(m>>11)*N + n]  (max over points)
template<int MODE>
__global__ __launch_bounds__(256, 2)
void gemm_fused(const float* __restrict__ A, const float* __restrict__ W,
                const float* __restrict__ bias, const float* __restrict__ gamma,
                const float* __restrict__ beta, const float* __restrict__ resIn,
                float* __restrict__ out, int M, int K, int N)
{
    __shared__ float As[2][8][128];
    __shared__ float Bs[2][8][132];
    int tid = threadIdx.x;
    int row0 = blockIdx.y * 128, col0 = blockIdx.x * 128;
    int tx = tid & 15, ty = tid >> 4;
    float acc[8][8];
    #pragma unroll
    for (int i = 0; i < 8; i++)
        #pragma unroll
        for (int j = 0; j < 8; j++) acc[i][j] = 0.f;

    int aRow = tid >> 1;          // 0..127
    int aCol = (tid & 1) * 4;     // 0 or 4
    int bRow = tid >> 5;          // 0..7
    int bCol = (tid & 31) * 4;    // 0..124

    const float* Ap = A + (size_t)(row0 + aRow)*K + aCol;
    const float* Wp = W + (size_t)bRow*N;

    // ---- preload tile 0 ----
    {
        float4 a4 = *reinterpret_cast<const float4*>(Ap);
        As[0][aCol+0][aRow] = a4.x; As[0][aCol+1][aRow] = a4.y;
        As[0][aCol+2][aRow] = a4.z; As[0][aCol+3][aRow] = a4.w;
        #pragma unroll
        for (int q = 0; q < 4; q++) {
            int cg = col0 + bCol + q;
            Bs[0][bRow][bCol+q] = (cg < N) ? Wp[cg] : 0.f;
        }
    }
    __syncthreads();

    int buf = 0;
    for (int k0 = 0; k0 < K; k0 += 8) {
        bool more = (k0 + 8) < K;
        float4 a4n;
        float b4n[4];
        if (more) {
            a4n = *reinterpret_cast<const float4*>(Ap + k0 + 8);
            const float* Wn = Wp + (size_t)(k0 + 8)*N;
            #pragma unroll
            for (int q = 0; q < 4; q++) {
                int cg = col0 + bCol + q;
                b4n[q] = (cg < N) ? Wn[cg] : 0.f;
            }
        }
        #pragma unroll
        for (int kk = 0; kk < 8; kk++) {
            float a[8], bb[8];
            float4 av0 = *reinterpret_cast<float4*>(&As[buf][kk][ty*8]);
            float4 av1 = *reinterpret_cast<float4*>(&As[buf][kk][ty*8+4]);
            float4 bv0 = *reinterpret_cast<float4*>(&Bs[buf][kk][tx*8]);
            float4 bv1 = *reinterpret_cast<float4*>(&Bs[buf][kk][tx*8+4]);
            a[0]=av0.x; a[1]=av0.y; a[2]=av0.z; a[3]=av0.w;
            a[4]=av1.x; a[5]=av1.y; a[6]=av1.z; a[7]=av1.w;
            bb[0]=bv0.x; bb[1]=bv0.y; bb[2]=bv0.z; bb[3]=bv0.w;
            bb[4]=bv1.x; bb[5]=bv1.y; bb[6]=bv1.z; bb[7]=bv1.w;
            #pragma unroll
            for (int i = 0; i < 8; i++)
                #pragma unroll
                for (int j = 0; j < 8; j++)
                    acc[i][j] += a[i]*bb[j];
        }
        if (more) {
            int nb = buf ^ 1;
            As[nb][aCol+0][aRow] = a4n.x; As[nb][aCol+1][aRow] = a4n.y;
            As[nb][aCol+2][aRow] = a4n.z; As[nb][aCol+3][aRow] = a4n.w;
            #pragma unroll
            for (int q = 0; q < 4; q++) Bs[nb][bRow][bCol+q] = b4n[q];
            __syncthreads();
            buf = nb;
        }
    }

    #pragma unroll
    for (int i = 0; i < 8; i++) {
        int m = row0 + ty*8 + i;
        #pragma unroll
        for (int j = 0; j < 8; j++) {
            int n = col0 + tx*8 + j;
            if (n >= N) continue;
            float v = acc[i][j];
            if (MODE == 0) {
                float al = gamma[n]*BNS;
                v = fmaxf(v*al + (bias[n]*al + beta[n]), 0.f);
                out[(size_t)m*N + n] = v;
            } else if (MODE == 1) {
                out[(size_t)m*N + n] = resIn[(size_t)m*N + n] + v + bias[n];
            } else {
                float al = gamma[n]*BNS;
                v = fmaxf(v*al + (bias[n]*al + beta[n]), 0.f);
                atomicMax((unsigned int*)&out[(size_t)(m >> 11)*N + n], __float_as_uint(v));
            }
        }
    }
}

__global__ void init_out(float* out) {
    int i = blockIdx.x*256 + threadIdx.x;
    if (i < B*170) out[i] = 0.f;
}

// ---------------- launch ----------------
extern "C" void kernel_launch(void* const* d_in, const int* in_sizes, int n_in,
                              void* d_out, int out_size)
{
    const float* points = (const float*)d_in[0];
    const float* noise  = (const float*)d_in[1];
    const float* tw   = (const float*)d_in[2];
    const float* tb   = (const float*)d_in[3];
    const float* tg1  = (const float*)d_in[4];
    const float* tbt1 = (const float*)d_in[5];
    const float* td1w = (const float*)d_in[6];
    const float* td1b = (const float*)d_in[7];
    const float* tg2  = (const float*)d_in[8];
    const float* tbt2 = (const float*)d_in[9];
    const float* td2w = (const float*)d_in[10];
    const float* td2b = (const float*)d_in[11];
    const float* c1w  = (const float*)d_in[12];
    const float* c1b  = (const float*)d_in[13];
    const float* g1   = (const float*)d_in[14];
    const float* be1  = (const float*)d_in[15];
    const float* rw   = (const float*)d_in[16];
    const float* rb   = (const float*)d_in[17];
    const float* b1w  = (const float*)d_in[18];
    const float* b1b  = (const float*)d_in[19];
    const float* b1g  = (const float*)d_in[20];
    const float* b1be = (const float*)d_in[21];
    const float* b2w  = (const float*)d_in[22];
    const float* b2b  = (const float*)d_in[23];
    const float* b2g  = (const float*)d_in[24];
    const float* b2be = (const float*)d_in[25];
    const float* b3w  = (const float*)d_in[26];
    const float* b3b  = (const float*)d_in[27];
    const float* b3g  = (const float*)d_in[28];
    const float* b3be = (const float*)d_in[29];
    float* out = (float*)d_out;

    float *xmax, *Tm, *feats, *f0, *f1;
    cudaGetSymbolAddress((void**)&xmax,  g_xmax);
    cudaGetSymbolAddress((void**)&Tm,    g_T);
    cudaGetSymbolAddress((void**)&feats, g_feats);
    cudaGetSymbolAddress((void**)&f0,    g_f0);
    cudaGetSymbolAddress((void**)&f1,    g_f1);

    // launch order chosen so ballquery_kernel sits at profiled launch index 3
    init_out<<<(B*170 + 255)/256, 256>>>(out);                       // 0
    tnet_conv_max<<<B, TU>>>(points, tw, tb, tg1, tbt1, xmax);       // 1
    tnet_dense<<<B, TU>>>(xmax, td1w, td1b, tg2, tbt2, td2w, td2b, Tm); // 2

    const int SMEM_SEL = (NP*3 + NP + NP)*4 + NP*8 + KNN*4;  // 57600 B
    cudaFuncSetAttribute(ballquery_kernel, cudaFuncAttributeMaxDynamicSharedMemorySize, SMEM_SEL);
    ballquery_kernel<<<M_TOT, 256, SMEM_SEL>>>(points, noise, feats); // 3  <- profiled

    // MLP stack (proven fp32 double-buffered path)
    gemm_fused<0><<<dim3(4,128), 256>>>(feats, c1w, c1b, g1, be1, nullptr, f0, M_TOT, FEAT, 512);
    gemm_fused<1><<<dim3(4,128), 256>>>(f0, rw, rb, nullptr, nullptr, f0, f1, M_TOT, 512, 512);
    gemm_fused<0><<<dim3(4,128), 256>>>(f1, b1w, b1b, b1g, b1be, nullptr, f0, M_TOT, 512, 512);
    gemm_fused<0><<<dim3(2,128), 256>>>(f0, b2w, b2b, b2g, b2be, nullptr, f1, M_TOT, 512, 256);
    gemm_fused<2><<<dim3(2,128), 256>>>(f1, b3w, b3b, b3g, b3be, nullptr, out, M_TOT, 256, 170);
}